// round 4
// baseline (speedup 1.0000x reference)
#include <cuda_runtime.h>
#include <cuda_bf16.h>
#include <cstdint>

// VQ on GB300 via legacy mma.sync (compute_103-safe, no tcgen05):
// bf16x3 split distance-GEMM + packed-index argmin + exact fp32 fallback.

#define NROWS  131072
#define CDIM   64
#define NE     1024
#define MT     128              // rows per CTA
#define TPB    256
#define NBLK   (NROWS/MT)       // 1024
#define NCHUNK 8                // 8 chunks x 128 codes
#define GAPTH  0.25f

typedef unsigned int u32;

__device__ unsigned char g_Bhi[NE * CDIM * 2];   // [chunk128][n][k] bf16, SW128-swizzled
__device__ unsigned char g_Blo[NE * CDIM * 2];
__device__ float  g_e2[NE];
__device__ double g_loss_acc;
__device__ int    g_fb_cnt;
__device__ int    g_fb_rows[NROWS];

#define SW128(x) ((x) ^ (((x) >> 3) & 0x70))

__device__ __forceinline__ u32 smaddr(const void* p) {
    u32 a;
    asm("{ .reg .u64 t; cvta.to.shared.u64 t, %1; cvt.u32.u64 %0, t; }" : "=r"(a) : "l"(p));
    return a;
}
__device__ __forceinline__ void cpa16(u32 sd, const void* src) {
    asm volatile("cp.async.cg.shared.global [%0], [%1], 16;" :: "r"(sd), "l"(src));
}
#define CPA_COMMIT() asm volatile("cp.async.commit_group;")
#define CPA_WAIT0()  asm volatile("cp.async.wait_group 0;" ::: "memory")
#define CPA_WAIT1()  asm volatile("cp.async.wait_group 1;" ::: "memory")

__device__ __forceinline__ void ldsm4(u32* r, u32 addr) {
    asm volatile("ldmatrix.sync.aligned.m8n8.x4.shared.b16 {%0,%1,%2,%3}, [%4];"
                 : "=r"(r[0]), "=r"(r[1]), "=r"(r[2]), "=r"(r[3]) : "r"(addr));
}
__device__ __forceinline__ void mma16816(float* c, const u32* a, const u32* b) {
    asm volatile("mma.sync.aligned.m16n8k16.row.col.f32.bf16.bf16.f32 "
                 "{%0,%1,%2,%3}, {%4,%5,%6,%7}, {%8,%9}, {%0,%1,%2,%3};"
                 : "+f"(c[0]), "+f"(c[1]), "+f"(c[2]), "+f"(c[3])
                 : "r"(a[0]), "r"(a[1]), "r"(a[2]), "r"(a[3]), "r"(b[0]), "r"(b[1]));
}
__device__ __forceinline__ u32 bits2(__nv_bfloat162 h) { return *reinterpret_cast<u32*>(&h); }
__device__ __forceinline__ void split2(float x, float y, u32& hi, u32& lo) {
    __nv_bfloat162 h2 = __floats2bfloat162_rn(x, y);
    hi = bits2(h2);
    lo = bits2(__floats2bfloat162_rn(x - __bfloat162float(h2.x),
                                     y - __bfloat162float(h2.y)));
}

// ---- prep: codebook split/swizzle (128-code chunks) + norms; zero accums ----
__global__ void vq_prep_e(const float* __restrict__ embs) {
    int t = blockIdx.x * 256 + threadIdx.x;   // 8192 = 1024 codes x 8 k-chunks
    int c = t >> 3, kc = t & 7;
    const float4* s = (const float4*)(embs + (size_t)c * CDIM + kc * 8);
    float4 a = s[0], b = s[1];
    float f[8] = { a.x, a.y, a.z, a.w, b.x, b.y, b.z, b.w };
    u32 hi[4], lo[4];
    #pragma unroll
    for (int j = 0; j < 4; j++) split2(f[2*j], f[2*j+1], hi[j], lo[j]);
    size_t off = (size_t)(c >> 7) * 16384 + SW128((c & 127) * 128 + kc * 16);
    *(uint4*)(g_Bhi + off) = make_uint4(hi[0], hi[1], hi[2], hi[3]);
    *(uint4*)(g_Blo + off) = make_uint4(lo[0], lo[1], lo[2], lo[3]);
    if (kc == 0) {
        const float4* p = (const float4*)(embs + (size_t)c * CDIM);
        float e2 = 0.f;
        #pragma unroll
        for (int q = 0; q < 16; q++) {
            float4 v = p[q];
            e2 += v.x * v.x + v.y * v.y + v.z * v.z + v.w * v.w;
        }
        g_e2[c] = e2;
    }
    if (t == 0) { g_loss_acc = 0.0; g_fb_cnt = 0; }
}

// ---- smem layout ----
#define SM_E2   0                 // 4KB  e2[1024]
#define SM_M1   4096              // 1KB  [2][128]
#define SM_M2   5120              // 1KB
#define SM_RED  6144              // 32B
#define SM_B    8192              // 2 x (16KB hi + 16KB lo)
#define SMEM_SZ (8192 + 65536)

__global__ __launch_bounds__(TPB, 2) void vq_main(
    const float* __restrict__ ze, const float* __restrict__ embs,
    float* __restrict__ out)
{
    extern __shared__ unsigned char sm[];
    const u32 sb  = smaddr(sm);
    const int tid = threadIdx.x;
    const int w   = tid >> 5;
    const int ln  = tid & 31;
    const int rg  = w & 3;            // row group: rows rg*32..rg*32+31
    const int cg  = w >> 2;           // code half within each chunk
    const int m0  = rg * 32;
    const size_t row0 = (size_t)blockIdx.x * MT;

    // prologue: e2 + chunk0 (group 0), chunk1 (group 1)
    cpa16(sb + SM_E2 + tid * 16, (const unsigned char*)g_e2 + tid * 16);
    #pragma unroll
    for (int i = 0; i < 4; i++) {
        cpa16(sb + SM_B + i * 4096 + tid * 16,         g_Bhi + i * 4096 + tid * 16);
        cpa16(sb + SM_B + 16384 + i * 4096 + tid * 16, g_Blo + i * 4096 + tid * 16);
    }
    CPA_COMMIT();
    #pragma unroll
    for (int i = 0; i < 4; i++) {
        cpa16(sb + SM_B + 32768 + i * 4096 + tid * 16,         g_Bhi + 16384 + i * 4096 + tid * 16);
        cpa16(sb + SM_B + 32768 + 16384 + i * 4096 + tid * 16, g_Blo + 16384 + i * 4096 + tid * 16);
    }
    CPA_COMMIT();

    // A fragments (rows m0..m0+31, K=64) resident in registers, hi+lo
    u32 Ahi[2][4][4], Alo[2][4][4];
    {
        const float2* zp = (const float2*)ze;
        #pragma unroll
        for (int mt = 0; mt < 2; mt++)
            #pragma unroll
            for (int ks = 0; ks < 4; ks++) {
                size_t rA = row0 + m0 + mt * 16 + (ln >> 2);
                int kp = ks * 8 + (ln & 3);          // float2 index (k/2)
                float2 v0 = zp[rA * 32 + kp];
                float2 v1 = zp[(rA + 8) * 32 + kp];
                float2 v2 = zp[rA * 32 + kp + 4];
                float2 v3 = zp[(rA + 8) * 32 + kp + 4];
                split2(v0.x, v0.y, Ahi[mt][ks][0], Alo[mt][ks][0]);
                split2(v1.x, v1.y, Ahi[mt][ks][1], Alo[mt][ks][1]);
                split2(v2.x, v2.y, Ahi[mt][ks][2], Alo[mt][ks][2]);
                split2(v3.x, v3.y, Ahi[mt][ks][3], Alo[mt][ks][3]);
            }
    }

    // ldmatrix lane offsets (SW128 within a 16KB chunk)
    u32 xo0 = (u32)((ln & 7) * 128 + 16 * (ln >> 3));
    u32 xo1 = xo0 + 64;
    const u32 lane0 = SW128(xo0), lane1 = SW128(xo1);

    float m1[4], m2[4];
    #pragma unroll
    for (int s = 0; s < 4; s++) { m1[s] = 3.4e38f; m2[s] = 3.4e38f; }

    const float* e2s = (const float*)(sm + SM_E2);

    for (int t = 0; t < NCHUNK; t++) {
        const int b = t & 1;
        if (t < NCHUNK - 1) CPA_WAIT1(); else CPA_WAIT0();
        __syncthreads();

        const u32 bhi = sb + SM_B + b * 32768;
        const u32 blo = bhi + 16384;

        #pragma unroll
        for (int nt = 0; nt < 8; nt++) {
            const int nl = cg * 64 + nt * 8;       // code offset within chunk
            u32 bh[8], bl[8];
            ldsm4(bh,     bhi + nl * 128 + lane0);
            ldsm4(bh + 4, bhi + nl * 128 + lane1);
            ldsm4(bl,     blo + nl * 128 + lane0);
            ldsm4(bl + 4, blo + nl * 128 + lane1);

            float acc[2][4];
            #pragma unroll
            for (int mt = 0; mt < 2; mt++)
                #pragma unroll
                for (int j = 0; j < 4; j++) acc[mt][j] = 0.f;

            #pragma unroll
            for (int ks = 0; ks < 4; ks++) {
                mma16816(acc[0], Ahi[0][ks], &bh[ks * 2]);
                mma16816(acc[1], Ahi[1][ks], &bh[ks * 2]);
                mma16816(acc[0], Alo[0][ks], &bh[ks * 2]);
                mma16816(acc[1], Alo[1][ks], &bh[ks * 2]);
                mma16816(acc[0], Ahi[0][ks], &bl[ks * 2]);
                mma16816(acc[1], Ahi[1][ks], &bl[ks * 2]);
            }

            // distances + packed-index running min1/min2
            const int c0 = t * 128 + nl + 2 * (ln & 3);
            float2 e2v = *(const float2*)(e2s + c0);
            #pragma unroll
            for (int mt = 0; mt < 2; mt++)
                #pragma unroll
                for (int rh = 0; rh < 2; rh++) {
                    const int s = mt * 2 + rh;
                    float d0 = fmaf(acc[mt][rh * 2],     -2.f, e2v.x);
                    float d1 = fmaf(acc[mt][rh * 2 + 1], -2.f, e2v.y);
                    float q0 = __uint_as_float((__float_as_uint(d0) & 0xFFFFFC00u) | (u32)c0);
                    float q1 = __uint_as_float((__float_as_uint(d1) & 0xFFFFFC00u) | (u32)(c0 + 1));
                    m2[s] = fminf(m2[s], fmaxf(m1[s], q0));
                    m1[s] = fminf(m1[s], q0);
                    m2[s] = fminf(m2[s], fmaxf(m1[s], q1));
                    m1[s] = fminf(m1[s], q1);
                }
        }
        __syncthreads();
        if (t + 2 < NCHUNK) {       // refill freed buffer
            const u32 d = sb + SM_B + b * 32768;
            const size_t goff = (size_t)(t + 2) * 16384;
            #pragma unroll
            for (int i = 0; i < 4; i++) {
                cpa16(d + i * 4096 + tid * 16,         g_Bhi + goff + i * 4096 + tid * 16);
                cpa16(d + 16384 + i * 4096 + tid * 16, g_Blo + goff + i * 4096 + tid * 16);
            }
            CPA_COMMIT();
        }
    }

    // merge across the 4 lanes sharing each row (lane bits 0,1)
    #pragma unroll
    for (int s = 0; s < 4; s++) {
        #pragma unroll
        for (int d = 1; d <= 2; d <<= 1) {
            float o1 = __shfl_xor_sync(0xffffffffu, m1[s], d);
            float o2 = __shfl_xor_sync(0xffffffffu, m2[s], d);
            m2[s] = fminf(fminf(m2[s], o2), fmaxf(m1[s], o1));
            m1[s] = fminf(m1[s], o1);
        }
    }
    float* sm1 = (float*)(sm + SM_M1);
    float* sm2 = (float*)(sm + SM_M2);
    if ((ln & 3) == 0) {
        #pragma unroll
        for (int s = 0; s < 4; s++) {
            int r = m0 + (s >> 1) * 16 + (s & 1) * 8 + (ln >> 2);
            sm1[cg * 128 + r] = m1[s];
            sm2[cg * 128 + r] = m2[s];
        }
    }
    __syncthreads();

    float* sred = (float*)(sm + SM_RED);
    float ls = 0.f;
    if (w < 4) {
        const int r = w * 32 + ln;
        float a1 = sm1[r], a2 = sm2[r], b1 = sm1[128 + r], b2 = sm2[128 + r];
        float f1 = fminf(a1, b1);
        float f2 = fminf(fminf(a2, b2), fmaxf(a1, b1));
        if (f2 - f1 < GAPTH) {
            int p = atomicAdd(&g_fb_cnt, 1);
            g_fb_rows[p] = (int)(row0 + r);
        } else {
            int code = (int)(__float_as_uint(f1) & 0x3FFu);
            const float4* e4 = (const float4*)(embs + (size_t)code * CDIM);
            const float4* z4 = (const float4*)(ze + (row0 + r) * CDIM);
            float4*       o4 = (float4*)(out + (row0 + r) * CDIM);
            #pragma unroll
            for (int q = 0; q < 16; q++) {
                float4 e = e4[q], z = z4[q];
                o4[q] = e;
                float d0 = e.x - z.x, d1 = e.y - z.y, d2 = e.z - z.z, d3 = e.w - z.w;
                ls += d0 * d0 + d1 * d1 + d2 * d2 + d3 * d3;
            }
        }
    }
    #pragma unroll
    for (int off = 16; off > 0; off >>= 1)
        ls += __shfl_down_sync(0xffffffffu, ls, off);
    if (ln == 0 && w < 4) sred[w] = ls;
    __syncthreads();
    if (tid == 0)
        atomicAdd(&g_loss_acc, (double)(sred[0] + sred[1] + sred[2] + sred[3]));
}

// ---- exact fp32 fallback for ambiguous rows ----
__global__ void vq_fb(const float* __restrict__ ze, const float* __restrict__ embs,
                      float* __restrict__ out)
{
    const int n  = g_fb_cnt;
    const int wg = (blockIdx.x * blockDim.x + threadIdx.x) >> 5;
    const int ln = threadIdx.x & 31;
    const int nw = (gridDim.x * blockDim.x) >> 5;

    for (int i = wg; i < n; i += nw) {
        const int row = g_fb_rows[i];
        const float4* z4 = (const float4*)(ze + (size_t)row * CDIM);
        float4 zr[16];
        float zn = 0.f;
        #pragma unroll
        for (int q = 0; q < 16; q++) {
            zr[q] = z4[q];
            zn += zr[q].x * zr[q].x + zr[q].y * zr[q].y + zr[q].z * zr[q].z + zr[q].w * zr[q].w;
        }
        float best = 3.4e38f; int bi = 1 << 30;
        for (int c = ln; c < NE; c += 32) {
            const float4* e4 = (const float4*)(embs + (size_t)c * CDIM);
            float dt = 0.f, e2 = 0.f;
            #pragma unroll
            for (int q = 0; q < 16; q++) {
                float4 e = e4[q];
                dt = fmaf(e.x, zr[q].x, dt); dt = fmaf(e.y, zr[q].y, dt);
                dt = fmaf(e.z, zr[q].z, dt); dt = fmaf(e.w, zr[q].w, dt);
                e2 = fmaf(e.x, e.x, e2);     e2 = fmaf(e.y, e.y, e2);
                e2 = fmaf(e.z, e.z, e2);     e2 = fmaf(e.w, e.w, e2);
            }
            float dist = fmaf(dt, -2.f, zn + e2);
            if (dist < best) { best = dist; bi = c; }
        }
        #pragma unroll
        for (int off = 16; off > 0; off >>= 1) {
            float ob = __shfl_down_sync(0xffffffffu, best, off);
            int   oi = __shfl_down_sync(0xffffffffu, bi, off);
            if (ob < best || (ob == best && oi < bi)) { best = ob; bi = oi; }
        }
        bi = __shfl_sync(0xffffffffu, bi, 0);

        float2 ev = ((const float2*)(embs + (size_t)bi * CDIM))[ln];
        float2 zv = ((const float2*)(ze + (size_t)row * CDIM))[ln];
        ((float2*)(out + (size_t)row * CDIM))[ln] = ev;
        float d0 = ev.x - zv.x, d1 = ev.y - zv.y;
        float ls = d0 * d0 + d1 * d1;
        #pragma unroll
        for (int off = 16; off > 0; off >>= 1)
            ls += __shfl_down_sync(0xffffffffu, ls, off);
        if (ln == 0) atomicAdd(&g_loss_acc, (double)ls);
    }
}

__global__ void vq_fin(float* loss_out) {
    *loss_out = (float)(1.25 * g_loss_acc / (double)((long long)NROWS * CDIM));
}

extern "C" void kernel_launch(void* const* d_in, const int* in_sizes, int n_in,
                              void* d_out, int out_size) {
    const float* ze   = (const float*)d_in[0];
    const float* embs = (const float*)d_in[1];
    float* out = (float*)d_out;

    cudaFuncSetAttribute(vq_main, cudaFuncAttributeMaxDynamicSharedMemorySize, SMEM_SZ);

    vq_prep_e<<<NE * 8 / 256, 256>>>(embs);
    vq_main<<<NBLK, TPB, SMEM_SZ>>>(ze, embs, out);
    vq_fb<<<256, 256>>>(ze, embs, out);
    if (out_size > NROWS * CDIM)
        vq_fin<<<1, 1>>>(out + (out_size - 1));
}

// round 5
// speedup vs baseline: 1.0542x; 1.0542x over previous
#include <cuda_runtime.h>
#include <cuda_bf16.h>
#include <cstdint>

// VQ on GB300 via legacy mma.sync (compute_103-safe):
// 2-pass bf16 split distance-GEMM (z = zh+zl, e ~= eh) with 4 independent
// MMA chains per warp + packed-index argmin + exact fp32 fallback.

#define NROWS  131072
#define CDIM   64
#define NE     1024
#define MT     128              // rows per CTA
#define TPB    256
#define NBLK   (NROWS/MT)       // 1024
#define NCHUNK 8                // 8 chunks x 128 codes
#define GAPTH  0.25f

typedef unsigned int u32;

__device__ unsigned char g_Bhi[NE * CDIM * 2];   // [chunk128][n][k] bf16, SW128-swizzled
__device__ float  g_e2[NE];
__device__ double g_loss_acc;
__device__ int    g_fb_cnt;
__device__ int    g_fb_rows[NROWS];

#define SW128(x) ((x) ^ (((x) >> 3) & 0x70))

__device__ __forceinline__ u32 smaddr(const void* p) {
    u32 a;
    asm("{ .reg .u64 t; cvta.to.shared.u64 t, %1; cvt.u32.u64 %0, t; }" : "=r"(a) : "l"(p));
    return a;
}
__device__ __forceinline__ void cpa16(u32 sd, const void* src) {
    asm volatile("cp.async.cg.shared.global [%0], [%1], 16;" :: "r"(sd), "l"(src));
}
#define CPA_COMMIT() asm volatile("cp.async.commit_group;")
#define CPA_WAIT0()  asm volatile("cp.async.wait_group 0;" ::: "memory")
#define CPA_WAIT1()  asm volatile("cp.async.wait_group 1;" ::: "memory")

__device__ __forceinline__ void ldsm4(u32* r, u32 addr) {
    asm volatile("ldmatrix.sync.aligned.m8n8.x4.shared.b16 {%0,%1,%2,%3}, [%4];"
                 : "=r"(r[0]), "=r"(r[1]), "=r"(r[2]), "=r"(r[3]) : "r"(addr));
}
__device__ __forceinline__ void mma16816(float* c, const u32* a, const u32* b) {
    asm volatile("mma.sync.aligned.m16n8k16.row.col.f32.bf16.bf16.f32 "
                 "{%0,%1,%2,%3}, {%4,%5,%6,%7}, {%8,%9}, {%0,%1,%2,%3};"
                 : "+f"(c[0]), "+f"(c[1]), "+f"(c[2]), "+f"(c[3])
                 : "r"(a[0]), "r"(a[1]), "r"(a[2]), "r"(a[3]), "r"(b[0]), "r"(b[1]));
}
__device__ __forceinline__ u32 bits2(__nv_bfloat162 h) { return *reinterpret_cast<u32*>(&h); }
__device__ __forceinline__ void split2(float x, float y, u32& hi, u32& lo) {
    __nv_bfloat162 h2 = __floats2bfloat162_rn(x, y);
    hi = bits2(h2);
    lo = bits2(__floats2bfloat162_rn(x - __bfloat162float(h2.x),
                                     y - __bfloat162float(h2.y)));
}

// ---- prep: codebook bf16 + swizzle (128-code chunks) + norms; zero accums ----
__global__ void vq_prep_e(const float* __restrict__ embs) {
    int t = blockIdx.x * 256 + threadIdx.x;   // 8192 = 1024 codes x 8 k-chunks
    int c = t >> 3, kc = t & 7;
    const float4* s = (const float4*)(embs + (size_t)c * CDIM + kc * 8);
    float4 a = s[0], b = s[1];
    u32 hi[4];
    hi[0] = bits2(__floats2bfloat162_rn(a.x, a.y));
    hi[1] = bits2(__floats2bfloat162_rn(a.z, a.w));
    hi[2] = bits2(__floats2bfloat162_rn(b.x, b.y));
    hi[3] = bits2(__floats2bfloat162_rn(b.z, b.w));
    size_t off = (size_t)(c >> 7) * 16384 + SW128((c & 127) * 128 + kc * 16);
    *(uint4*)(g_Bhi + off) = make_uint4(hi[0], hi[1], hi[2], hi[3]);
    if (kc == 0) {
        const float4* p = (const float4*)(embs + (size_t)c * CDIM);
        float e2 = 0.f;
        #pragma unroll
        for (int q = 0; q < 16; q++) {
            float4 v = p[q];
            e2 += v.x * v.x + v.y * v.y + v.z * v.z + v.w * v.w;
        }
        g_e2[c] = e2;
    }
    if (t == 0) { g_loss_acc = 0.0; g_fb_cnt = 0; }
}

// ---- smem layout ----
#define SM_E2   0                 // 4KB  e2[1024]
#define SM_M1   4096              // 1KB  [2][128]
#define SM_M2   5120              // 1KB
#define SM_RED  6144              // 32B
#define SM_B    8192              // 2 x 16KB (hi only)
#define SMEM_SZ (8192 + 32768)

__global__ __launch_bounds__(TPB, 2) void vq_main(
    const float* __restrict__ ze, const float* __restrict__ embs,
    float* __restrict__ out)
{
    extern __shared__ unsigned char sm[];
    const u32 sb  = smaddr(sm);
    const int tid = threadIdx.x;
    const int w   = tid >> 5;
    const int ln  = tid & 31;
    const int rg  = w & 3;            // row group: rows rg*32..rg*32+31
    const int cg  = w >> 2;           // code half within each chunk
    const int m0  = rg * 32;
    const size_t row0 = (size_t)blockIdx.x * MT;

    // prologue: e2 + chunk0 (group 0), chunk1 (group 1)
    cpa16(sb + SM_E2 + tid * 16, (const unsigned char*)g_e2 + tid * 16);
    #pragma unroll
    for (int i = 0; i < 4; i++)
        cpa16(sb + SM_B + i * 4096 + tid * 16, g_Bhi + i * 4096 + tid * 16);
    CPA_COMMIT();
    #pragma unroll
    for (int i = 0; i < 4; i++)
        cpa16(sb + SM_B + 16384 + i * 4096 + tid * 16, g_Bhi + 16384 + i * 4096 + tid * 16);
    CPA_COMMIT();

    // A fragments (rows m0..m0+31, K=64) resident in registers, hi+lo
    u32 Ahi[2][4][4], Alo[2][4][4];
    {
        const float2* zp = (const float2*)ze;
        #pragma unroll
        for (int mt = 0; mt < 2; mt++)
            #pragma unroll
            for (int ks = 0; ks < 4; ks++) {
                size_t rA = row0 + m0 + mt * 16 + (ln >> 2);
                int kp = ks * 8 + (ln & 3);          // float2 index (k/2)
                float2 v0 = zp[rA * 32 + kp];
                float2 v1 = zp[(rA + 8) * 32 + kp];
                float2 v2 = zp[rA * 32 + kp + 4];
                float2 v3 = zp[(rA + 8) * 32 + kp + 4];
                split2(v0.x, v0.y, Ahi[mt][ks][0], Alo[mt][ks][0]);
                split2(v1.x, v1.y, Ahi[mt][ks][1], Alo[mt][ks][1]);
                split2(v2.x, v2.y, Ahi[mt][ks][2], Alo[mt][ks][2]);
                split2(v3.x, v3.y, Ahi[mt][ks][3], Alo[mt][ks][3]);
            }
    }

    // ldmatrix lane offsets (SW128 within a 16KB chunk)
    u32 xo0 = (u32)((ln & 7) * 128 + 16 * (ln >> 3));
    u32 xo1 = xo0 + 64;
    const u32 lane0 = SW128(xo0), lane1 = SW128(xo1);

    float m1[4], m2[4];
    #pragma unroll
    for (int s = 0; s < 4; s++) { m1[s] = 3.4e38f; m2[s] = 3.4e38f; }

    const float* e2s = (const float*)(sm + SM_E2);

    for (int t = 0; t < NCHUNK; t++) {
        const int b = t & 1;
        if (t < NCHUNK - 1) CPA_WAIT1(); else CPA_WAIT0();
        __syncthreads();

        const u32 bhi = sb + SM_B + b * 16384;

        #pragma unroll
        for (int nt = 0; nt < 8; nt++) {
            const int nl = cg * 64 + nt * 8;       // code offset within chunk
            u32 bh[8];
            ldsm4(bh,     bhi + nl * 128 + lane0);
            ldsm4(bh + 4, bhi + nl * 128 + lane1);

            // 4 independent depth-4 chains: accA (zh) + accB (zl), per m-tile
            float accA[2][4], accB[2][4];
            #pragma unroll
            for (int mt = 0; mt < 2; mt++)
                #pragma unroll
                for (int j = 0; j < 4; j++) { accA[mt][j] = 0.f; accB[mt][j] = 0.f; }

            #pragma unroll
            for (int ks = 0; ks < 4; ks++) {
                mma16816(accA[0], Ahi[0][ks], &bh[ks * 2]);
                mma16816(accA[1], Ahi[1][ks], &bh[ks * 2]);
                mma16816(accB[0], Alo[0][ks], &bh[ks * 2]);
                mma16816(accB[1], Alo[1][ks], &bh[ks * 2]);
            }

            // distances + packed-index running min1/min2
            const int c0 = t * 128 + nl + 2 * (ln & 3);
            float2 e2v = *(const float2*)(e2s + c0);
            #pragma unroll
            for (int mt = 0; mt < 2; mt++)
                #pragma unroll
                for (int rh = 0; rh < 2; rh++) {
                    const int s = mt * 2 + rh;
                    float dot0 = accA[mt][rh * 2]     + accB[mt][rh * 2];
                    float dot1 = accA[mt][rh * 2 + 1] + accB[mt][rh * 2 + 1];
                    float d0 = fmaf(dot0, -2.f, e2v.x);
                    float d1 = fmaf(dot1, -2.f, e2v.y);
                    float q0 = __uint_as_float((__float_as_uint(d0) & 0xFFFFFC00u) | (u32)c0);
                    float q1 = __uint_as_float((__float_as_uint(d1) & 0xFFFFFC00u) | (u32)(c0 + 1));
                    m2[s] = fminf(m2[s], fmaxf(m1[s], q0));
                    m1[s] = fminf(m1[s], q0);
                    m2[s] = fminf(m2[s], fmaxf(m1[s], q1));
                    m1[s] = fminf(m1[s], q1);
                }
        }
        __syncthreads();
        if (t + 2 < NCHUNK) {       // refill freed buffer
            const u32 d = sb + SM_B + b * 16384;
            const size_t goff = (size_t)(t + 2) * 16384;
            #pragma unroll
            for (int i = 0; i < 4; i++)
                cpa16(d + i * 4096 + tid * 16, g_Bhi + goff + i * 4096 + tid * 16);
            CPA_COMMIT();
        }
    }

    // merge across the 4 lanes sharing each row (lane bits 0,1)
    #pragma unroll
    for (int s = 0; s < 4; s++) {
        #pragma unroll
        for (int d = 1; d <= 2; d <<= 1) {
            float o1 = __shfl_xor_sync(0xffffffffu, m1[s], d);
            float o2 = __shfl_xor_sync(0xffffffffu, m2[s], d);
            m2[s] = fminf(fminf(m2[s], o2), fmaxf(m1[s], o1));
            m1[s] = fminf(m1[s], o1);
        }
    }
    float* sm1 = (float*)(sm + SM_M1);
    float* sm2 = (float*)(sm + SM_M2);
    if ((ln & 3) == 0) {
        #pragma unroll
        for (int s = 0; s < 4; s++) {
            int r = m0 + (s >> 1) * 16 + (s & 1) * 8 + (ln >> 2);
            sm1[cg * 128 + r] = m1[s];
            sm2[cg * 128 + r] = m2[s];
        }
    }
    __syncthreads();

    float* sred = (float*)(sm + SM_RED);
    float ls = 0.f;
    if (w < 4) {
        const int r = w * 32 + ln;
        float a1 = sm1[r], a2 = sm2[r], b1 = sm1[128 + r], b2 = sm2[128 + r];
        float f1 = fminf(a1, b1);
        float f2 = fminf(fminf(a2, b2), fmaxf(a1, b1));
        if (f2 - f1 < GAPTH) {
            int p = atomicAdd(&g_fb_cnt, 1);
            g_fb_rows[p] = (int)(row0 + r);
        } else {
            int code = (int)(__float_as_uint(f1) & 0x3FFu);
            const float4* e4 = (const float4*)(embs + (size_t)code * CDIM);
            const float4* z4 = (const float4*)(ze + (row0 + r) * CDIM);
            float4*       o4 = (float4*)(out + (row0 + r) * CDIM);
            #pragma unroll
            for (int q = 0; q < 16; q++) {
                float4 e = e4[q], z = z4[q];
                o4[q] = e;
                float d0 = e.x - z.x, d1 = e.y - z.y, d2 = e.z - z.z, d3 = e.w - z.w;
                ls += d0 * d0 + d1 * d1 + d2 * d2 + d3 * d3;
            }
        }
    }
    #pragma unroll
    for (int off = 16; off > 0; off >>= 1)
        ls += __shfl_down_sync(0xffffffffu, ls, off);
    if (ln == 0 && w < 4) sred[w] = ls;
    __syncthreads();
    if (tid == 0)
        atomicAdd(&g_loss_acc, (double)(sred[0] + sred[1] + sred[2] + sred[3]));
}

// ---- exact fp32 fallback for ambiguous rows ----
__global__ void vq_fb(const float* __restrict__ ze, const float* __restrict__ embs,
                      float* __restrict__ out)
{
    const int n  = g_fb_cnt;
    const int wg = (blockIdx.x * blockDim.x + threadIdx.x) >> 5;
    const int ln = threadIdx.x & 31;
    const int nw = (gridDim.x * blockDim.x) >> 5;

    for (int i = wg; i < n; i += nw) {
        const int row = g_fb_rows[i];
        const float4* z4 = (const float4*)(ze + (size_t)row * CDIM);
        float4 zr[16];
        float zn = 0.f;
        #pragma unroll
        for (int q = 0; q < 16; q++) {
            zr[q] = z4[q];
            zn += zr[q].x * zr[q].x + zr[q].y * zr[q].y + zr[q].z * zr[q].z + zr[q].w * zr[q].w;
        }
        float best = 3.4e38f; int bi = 1 << 30;
        for (int c = ln; c < NE; c += 32) {
            const float4* e4 = (const float4*)(embs + (size_t)c * CDIM);
            float dt = 0.f, e2 = 0.f;
            #pragma unroll
            for (int q = 0; q < 16; q++) {
                float4 e = e4[q];
                dt = fmaf(e.x, zr[q].x, dt); dt = fmaf(e.y, zr[q].y, dt);
                dt = fmaf(e.z, zr[q].z, dt); dt = fmaf(e.w, zr[q].w, dt);
                e2 = fmaf(e.x, e.x, e2);     e2 = fmaf(e.y, e.y, e2);
                e2 = fmaf(e.z, e.z, e2);     e2 = fmaf(e.w, e.w, e2);
            }
            float dist = fmaf(dt, -2.f, zn + e2);
            if (dist < best) { best = dist; bi = c; }
        }
        #pragma unroll
        for (int off = 16; off > 0; off >>= 1) {
            float ob = __shfl_down_sync(0xffffffffu, best, off);
            int   oi = __shfl_down_sync(0xffffffffu, bi, off);
            if (ob < best || (ob == best && oi < bi)) { best = ob; bi = oi; }
        }
        bi = __shfl_sync(0xffffffffu, bi, 0);

        float2 ev = ((const float2*)(embs + (size_t)bi * CDIM))[ln];
        float2 zv = ((const float2*)(ze + (size_t)row * CDIM))[ln];
        ((float2*)(out + (size_t)row * CDIM))[ln] = ev;
        float d0 = ev.x - zv.x, d1 = ev.y - zv.y;
        float ls = d0 * d0 + d1 * d1;
        #pragma unroll
        for (int off = 16; off > 0; off >>= 1)
            ls += __shfl_down_sync(0xffffffffu, ls, off);
        if (ln == 0) atomicAdd(&g_loss_acc, (double)ls);
    }
}

__global__ void vq_fin(float* loss_out) {
    *loss_out = (float)(1.25 * g_loss_acc / (double)((long long)NROWS * CDIM));
}

extern "C" void kernel_launch(void* const* d_in, const int* in_sizes, int n_in,
                              void* d_out, int out_size) {
    const float* ze   = (const float*)d_in[0];
    const float* embs = (const float*)d_in[1];
    float* out = (float*)d_out;

    cudaFuncSetAttribute(vq_main, cudaFuncAttributeMaxDynamicSharedMemorySize, SMEM_SZ);

    vq_prep_e<<<NE * 8 / 256, 256>>>(embs);
    vq_main<<<NBLK, TPB, SMEM_SZ>>>(ze, embs, out);
    vq_fb<<<256, 256>>>(ze, embs, out);
    if (out_size > NROWS * CDIM)
        vq_fin<<<1, 1>>>(out + (out_size - 1));
}

// round 6
// speedup vs baseline: 1.0666x; 1.0117x over previous
#include <cuda_runtime.h>
#include <cuda_bf16.h>
#include <cstdint>

// VQ on GB300 via legacy mma.sync: 2-pass bf16 split distance-GEMM,
// 16-rows-per-warp tiles (~75 regs, no spills), packed-index argmin,
// exact fp32 fallback (e2-table accelerated) for small-gap rows.

#define NROWS  131072
#define CDIM   64
#define NE     1024
#define MT     128              // rows per CTA
#define TPB    256              // 8 warps x 16 rows
#define NBLK   (NROWS/MT)       // 1024
#define NCHUNK 8                // 8 chunks x 128 codes
#define GAPTH  0.25f

typedef unsigned int u32;

__device__ unsigned char g_Bhi[NE * CDIM * 2];   // [chunk128][code][k] bf16, SW128
__device__ float  g_e2[NE];
__device__ double g_loss_acc;
__device__ int    g_fb_cnt;
__device__ int    g_fb_rows[NROWS];

#define SW128(x) ((x) ^ (((x) >> 3) & 0x70))

__device__ __forceinline__ u32 smaddr(const void* p) {
    u32 a;
    asm("{ .reg .u64 t; cvta.to.shared.u64 t, %1; cvt.u32.u64 %0, t; }" : "=r"(a) : "l"(p));
    return a;
}
__device__ __forceinline__ void cpa16(u32 sd, const void* src) {
    asm volatile("cp.async.cg.shared.global [%0], [%1], 16;" :: "r"(sd), "l"(src));
}
#define CPA_COMMIT() asm volatile("cp.async.commit_group;")
#define CPA_WAIT0()  asm volatile("cp.async.wait_group 0;" ::: "memory")
#define CPA_WAIT1()  asm volatile("cp.async.wait_group 1;" ::: "memory")

__device__ __forceinline__ void ldsm4(u32* r, u32 addr) {
    asm volatile("ldmatrix.sync.aligned.m8n8.x4.shared.b16 {%0,%1,%2,%3}, [%4];"
                 : "=r"(r[0]), "=r"(r[1]), "=r"(r[2]), "=r"(r[3]) : "r"(addr));
}
__device__ __forceinline__ void mma16816(float* c, const u32* a, const u32* b) {
    asm volatile("mma.sync.aligned.m16n8k16.row.col.f32.bf16.bf16.f32 "
                 "{%0,%1,%2,%3}, {%4,%5,%6,%7}, {%8,%9}, {%0,%1,%2,%3};"
                 : "+f"(c[0]), "+f"(c[1]), "+f"(c[2]), "+f"(c[3])
                 : "r"(a[0]), "r"(a[1]), "r"(a[2]), "r"(a[3]), "r"(b[0]), "r"(b[1]));
}
__device__ __forceinline__ u32 bits2(__nv_bfloat162 h) { return *reinterpret_cast<u32*>(&h); }
__device__ __forceinline__ void split2(float x, float y, u32& hi, u32& lo) {
    __nv_bfloat162 h2 = __floats2bfloat162_rn(x, y);
    hi = bits2(h2);
    lo = bits2(__floats2bfloat162_rn(x - __bfloat162float(h2.x),
                                     y - __bfloat162float(h2.y)));
}

// ---- prep: codebook bf16 + SW128 swizzle per 128-code chunk + norms ----
__global__ void vq_prep_e(const float* __restrict__ embs) {
    int t = blockIdx.x * 256 + threadIdx.x;   // 8192 = 1024 codes x 8 k-chunks
    int c = t >> 3, kc = t & 7;
    const float4* s = (const float4*)(embs + (size_t)c * CDIM + kc * 8);
    float4 a = s[0], b = s[1];
    u32 hi[4];
    hi[0] = bits2(__floats2bfloat162_rn(a.x, a.y));
    hi[1] = bits2(__floats2bfloat162_rn(a.z, a.w));
    hi[2] = bits2(__floats2bfloat162_rn(b.x, b.y));
    hi[3] = bits2(__floats2bfloat162_rn(b.z, b.w));
    size_t off = (size_t)(c >> 7) * 16384 + SW128((c & 127) * 128 + kc * 16);
    *(uint4*)(g_Bhi + off) = make_uint4(hi[0], hi[1], hi[2], hi[3]);
    if (kc == 0) {
        const float4* p = (const float4*)(embs + (size_t)c * CDIM);
        float e2 = 0.f;
        #pragma unroll
        for (int q = 0; q < 16; q++) {
            float4 v = p[q];
            e2 += v.x * v.x + v.y * v.y + v.z * v.z + v.w * v.w;
        }
        g_e2[c] = e2;
    }
    if (t == 0) { g_loss_acc = 0.0; g_fb_cnt = 0; }
}

// ---- smem layout ----
#define SM_E2   0                 // 4KB  e2[1024]
#define SM_RED  4096              // 32B  per-warp loss partials
#define SM_B    8192              // 2 x 16KB double-buffered B chunks
#define SMEM_SZ (8192 + 32768)

__global__ __launch_bounds__(TPB) void vq_main(
    const float* __restrict__ ze, const float* __restrict__ embs,
    float* __restrict__ out)
{
    extern __shared__ unsigned char sm[];
    const u32 sb  = smaddr(sm);
    const int tid = threadIdx.x;
    const int w   = tid >> 5;
    const int ln  = tid & 31;
    const size_t row0 = (size_t)blockIdx.x * MT;

    // prologue: e2 + chunk0 (group 0), chunk1 (group 1)
    cpa16(sb + SM_E2 + tid * 16, (const unsigned char*)g_e2 + tid * 16);
    #pragma unroll
    for (int i = 0; i < 4; i++)
        cpa16(sb + SM_B + i * 4096 + tid * 16, g_Bhi + i * 4096 + tid * 16);
    CPA_COMMIT();
    #pragma unroll
    for (int i = 0; i < 4; i++)
        cpa16(sb + SM_B + 16384 + i * 4096 + tid * 16, g_Bhi + 16384 + i * 4096 + tid * 16);
    CPA_COMMIT();

    // A fragments: 16 rows (one m16 tile), K=64, hi+lo -> 32 regs
    u32 Ahi[4][4], Alo[4][4];
    {
        const float2* zp = (const float2*)ze;
        const size_t rA = row0 + w * 16 + (ln >> 2);
        #pragma unroll
        for (int ks = 0; ks < 4; ks++) {
            int kp = ks * 8 + (ln & 3);              // float2 index (k/2)
            float2 v0 = zp[rA * 32 + kp];
            float2 v1 = zp[(rA + 8) * 32 + kp];
            float2 v2 = zp[rA * 32 + kp + 4];
            float2 v3 = zp[(rA + 8) * 32 + kp + 4];
            split2(v0.x, v0.y, Ahi[ks][0], Alo[ks][0]);
            split2(v1.x, v1.y, Ahi[ks][1], Alo[ks][1]);
            split2(v2.x, v2.y, Ahi[ks][2], Alo[ks][2]);
            split2(v3.x, v3.y, Ahi[ks][3], Alo[ks][3]);
        }
    }

    // ldmatrix lane offsets (SW128 within a 16KB chunk)
    const u32 lane0 = SW128((u32)((ln & 7) * 128 + 16 * (ln >> 3)));
    const u32 lane1 = SW128((u32)((ln & 7) * 128 + 16 * (ln >> 3) + 64));

    float m1[2], m2[2];           // s=0: row ln>>2 ; s=1: row ln>>2 + 8
    m1[0] = m1[1] = 3.4e38f;
    m2[0] = m2[1] = 3.4e38f;

    const float* e2s = (const float*)(sm + SM_E2);

    for (int t = 0; t < NCHUNK; t++) {
        const int b = t & 1;
        if (t < NCHUNK - 1) CPA_WAIT1(); else CPA_WAIT0();
        __syncthreads();

        const u32 bhi = sb + SM_B + b * 16384;

        #pragma unroll 4
        for (int nt = 0; nt < 16; nt++) {
            const int nl = nt * 8;                 // 8 codes per n-tile
            u32 bh[8];
            ldsm4(bh,     bhi + nl * 128 + lane0);
            ldsm4(bh + 4, bhi + nl * 128 + lane1);

            float accA[4] = {0.f, 0.f, 0.f, 0.f};  // zh chain
            float accB[4] = {0.f, 0.f, 0.f, 0.f};  // zl chain
            #pragma unroll
            for (int ks = 0; ks < 4; ks++) {
                mma16816(accA, Ahi[ks], &bh[ks * 2]);
                mma16816(accB, Alo[ks], &bh[ks * 2]);
            }

            const int c0 = t * 128 + nl + 2 * (ln & 3);
            float2 e2v = *(const float2*)(e2s + c0);
            #pragma unroll
            for (int s = 0; s < 2; s++) {
                float d0 = fmaf(accA[s * 2]     + accB[s * 2],     -2.f, e2v.x);
                float d1 = fmaf(accA[s * 2 + 1] + accB[s * 2 + 1], -2.f, e2v.y);
                float q0 = __uint_as_float((__float_as_uint(d0) & 0xFFFFFC00u) | (u32)c0);
                float q1 = __uint_as_float((__float_as_uint(d1) & 0xFFFFFC00u) | (u32)(c0 + 1));
                m2[s] = fminf(m2[s], fmaxf(m1[s], q0));
                m1[s] = fminf(m1[s], q0);
                m2[s] = fminf(m2[s], fmaxf(m1[s], q1));
                m1[s] = fminf(m1[s], q1);
            }
        }
        __syncthreads();           // all warps done with buffer b
        if (t + 2 < NCHUNK) {      // refill it with chunk t+2
            const u32 d = sb + SM_B + b * 16384;
            const size_t goff = (size_t)(t + 2) * 16384;
            #pragma unroll
            for (int i = 0; i < 4; i++)
                cpa16(d + i * 4096 + tid * 16, g_Bhi + goff + i * 4096 + tid * 16);
            CPA_COMMIT();
        }
    }

    // merge the 4 lanes of each quad (code subsets); all lanes converge
    #pragma unroll
    for (int s = 0; s < 2; s++) {
        #pragma unroll
        for (int d = 1; d <= 2; d <<= 1) {
            float o1 = __shfl_xor_sync(0xffffffffu, m1[s], d);
            float o2 = __shfl_xor_sync(0xffffffffu, m2[s], d);
            m2[s] = fminf(fminf(m2[s], o2), fmaxf(m1[s], o1));
            m1[s] = fminf(m1[s], o1);
        }
    }

    // per-row output: whole warp cooperates, fully coalesced
    float ls = 0.f;
    #pragma unroll
    for (int r = 0; r < 16; r++) {
        const int src = (r & 7) * 4;
        float f1a = __shfl_sync(0xffffffffu, m1[0], src);
        float f1b = __shfl_sync(0xffffffffu, m1[1], src);
        float f2a = __shfl_sync(0xffffffffu, m2[0], src);
        float f2b = __shfl_sync(0xffffffffu, m2[1], src);
        float f1 = (r < 8) ? f1a : f1b;
        float f2 = (r < 8) ? f2a : f2b;
        const size_t grow = row0 + w * 16 + r;
        if (f2 - f1 < GAPTH) {
            if (ln == 0) { int p = atomicAdd(&g_fb_cnt, 1); g_fb_rows[p] = (int)grow; }
            continue;
        }
        int code = (int)(__float_as_uint(f1) & 0x3FFu);
        float2 e = ((const float2*)(embs + (size_t)code * CDIM))[ln];
        float2 z = ((const float2*)(ze + grow * CDIM))[ln];
        ((float2*)(out + grow * CDIM))[ln] = e;
        float d0 = e.x - z.x, d1 = e.y - z.y;
        ls += d0 * d0 + d1 * d1;
    }
    #pragma unroll
    for (int off = 16; off > 0; off >>= 1)
        ls += __shfl_down_sync(0xffffffffu, ls, off);
    float* sred = (float*)(sm + SM_RED);
    if (ln == 0) sred[w] = ls;
    __syncthreads();
    if (tid == 0) {
        float s = 0.f;
        #pragma unroll
        for (int i = 0; i < 8; i++) s += sred[i];
        atomicAdd(&g_loss_acc, (double)s);
    }
}

// ---- exact fp32 fallback (uses precomputed e2 table: 64 FMA/code) ----
__global__ void vq_fb(const float* __restrict__ ze, const float* __restrict__ embs,
                      float* __restrict__ out)
{
    const int n  = g_fb_cnt;
    const int wg = (blockIdx.x * blockDim.x + threadIdx.x) >> 5;
    const int ln = threadIdx.x & 31;
    const int nw = (gridDim.x * blockDim.x) >> 5;

    for (int i = wg; i < n; i += nw) {
        const int row = g_fb_rows[i];
        const float4* z4 = (const float4*)(ze + (size_t)row * CDIM);
        float4 zr[16];
        float zn = 0.f;
        #pragma unroll
        for (int q = 0; q < 16; q++) {
            zr[q] = z4[q];
            zn += zr[q].x * zr[q].x + zr[q].y * zr[q].y + zr[q].z * zr[q].z + zr[q].w * zr[q].w;
        }
        float best = 3.4e38f; int bi = 1 << 30;
        for (int c = ln; c < NE; c += 32) {
            const float4* e4 = (const float4*)(embs + (size_t)c * CDIM);
            float dt = 0.f;
            #pragma unroll
            for (int q = 0; q < 16; q++) {
                float4 e = e4[q];
                dt = fmaf(e.x, zr[q].x, dt); dt = fmaf(e.y, zr[q].y, dt);
                dt = fmaf(e.z, zr[q].z, dt); dt = fmaf(e.w, zr[q].w, dt);
            }
            float dist = fmaf(dt, -2.f, zn + g_e2[c]);
            if (dist < best) { best = dist; bi = c; }
        }
        #pragma unroll
        for (int off = 16; off > 0; off >>= 1) {
            float ob = __shfl_down_sync(0xffffffffu, best, off);
            int   oi = __shfl_down_sync(0xffffffffu, bi, off);
            if (ob < best || (ob == best && oi < bi)) { best = ob; bi = oi; }
        }
        bi = __shfl_sync(0xffffffffu, bi, 0);

        float2 ev = ((const float2*)(embs + (size_t)bi * CDIM))[ln];
        float2 zv = ((const float2*)(ze + (size_t)row * CDIM))[ln];
        ((float2*)(out + (size_t)row * CDIM))[ln] = ev;
        float d0 = ev.x - zv.x, d1 = ev.y - zv.y;
        float ls = d0 * d0 + d1 * d1;
        #pragma unroll
        for (int off = 16; off > 0; off >>= 1)
            ls += __shfl_down_sync(0xffffffffu, ls, off);
        if (ln == 0) atomicAdd(&g_loss_acc, (double)ls);
    }
}

__global__ void vq_fin(float* loss_out) {
    *loss_out = (float)(1.25 * g_loss_acc / (double)((long long)NROWS * CDIM));
}

extern "C" void kernel_launch(void* const* d_in, const int* in_sizes, int n_in,
                              void* d_out, int out_size) {
    const float* ze   = (const float*)d_in[0];
    const float* embs = (const float*)d_in[1];
    float* out = (float*)d_out;

    cudaFuncSetAttribute(vq_main, cudaFuncAttributeMaxDynamicSharedMemorySize, SMEM_SZ);

    vq_prep_e<<<NE * 8 / 256, 256>>>(embs);
    vq_main<<<NBLK, TPB, SMEM_SZ>>>(ze, embs, out);
    vq_fb<<<256, 256>>>(ze, embs, out);
    if (out_size > NROWS * CDIM)
        vq_fin<<<1, 1>>>(out + (out_size - 1));
}